// round 17
// baseline (speedup 1.0000x reference)
#include <cuda_runtime.h>
#include <cuda_bf16.h>
#include <cstdint>
#include <cstddef>

typedef unsigned long long u64;

#define BATCH 512
#define SEQT  1024
#define RTB   16

// ---------------- scratch (static device globals) -------------------------------
__device__ float g_g1[(size_t)BATCH * SEQT * 512];   // layer1 gate preacts (1.07 GB)
__device__ float g_g2[(size_t)BATCH * SEQT * 256];   // layer2-fwd gate preacts (536 MB)
__device__ float g_h1[(size_t)BATCH * SEQT * 128];   // layer1 h [fwd|bwd] fp32 (268 MB)
__device__ float g_h2[BATCH * 64];                   // layer2-fwd final h
__device__ __nv_bfloat16 g_wh[768 * 128];            // w_ih split-bf16 hi: l0d0,l0d1,l1d0
__device__ __nv_bfloat16 g_wl[768 * 128];            // w_ih split-bf16 lo

// ---------------- activations (single-MUFU) --------------------------------------
static __device__ __forceinline__ float tanh_ap(float x) {
    float y;
    asm("tanh.approx.f32 %0, %1;" : "=f"(y) : "f"(x));
    return y;
}
static __device__ __forceinline__ float sigf(float x) {
    return fmaf(tanh_ap(0.5f * x), 0.5f, 0.5f);
}
static __device__ __forceinline__ float tnhf(float x) {
    return tanh_ap(x);
}

// ---------------- mma.sync / ldmatrix helpers ------------------------------------
static __device__ __forceinline__ uint32_t smem_u32(const void* p) {
    uint32_t a;
    asm("{ .reg .u64 t; cvta.to.shared.u64 t, %1; cvt.u32.u64 %0, t; }" : "=r"(a) : "l"(p));
    return a;
}
#define LDSM4(d0, d1, d2, d3, a)                                                     \
    asm volatile("ldmatrix.sync.aligned.m8n8.x4.shared.b16 {%0,%1,%2,%3}, [%4];"     \
                 : "=r"(d0), "=r"(d1), "=r"(d2), "=r"(d3) : "r"(a))

static __device__ __forceinline__ void mma16816(float* d, const uint32_t* a,
                                                const uint32_t* b) {
    asm volatile(
        "mma.sync.aligned.m16n8k16.row.col.f32.bf16.bf16.f32 "
        "{%0,%1,%2,%3}, {%4,%5,%6,%7}, {%8,%9}, {%0,%1,%2,%3};"
        : "+f"(d[0]), "+f"(d[1]), "+f"(d[2]), "+f"(d[3])
        : "r"(a[0]), "r"(a[1]), "r"(a[2]), "r"(a[3]), "r"(b[0]), "r"(b[1]));
}

// split 8 fp32 -> bf16 hi/lo packed
static __device__ __forceinline__ void split8(const float* v, uint4& hi, uint4& lo) {
    unsigned hw[4], lw[4];
#pragma unroll
    for (int p = 0; p < 4; p++) {
        __nv_bfloat16 h0 = __float2bfloat16(v[2 * p]);
        __nv_bfloat16 h1 = __float2bfloat16(v[2 * p + 1]);
        float r0 = v[2 * p]     - __bfloat162float(h0);
        float r1 = v[2 * p + 1] - __bfloat162float(h1);
        __nv_bfloat16 l0 = __float2bfloat16(r0);
        __nv_bfloat16 l1 = __float2bfloat16(r1);
        hw[p] = (unsigned)(*(unsigned short*)&h0) | ((unsigned)(*(unsigned short*)&h1) << 16);
        lw[p] = (unsigned)(*(unsigned short*)&l0) | ((unsigned)(*(unsigned short*)&l1) << 16);
    }
    hi = make_uint4(hw[0], hw[1], hw[2], hw[3]);
    lo = make_uint4(lw[0], lw[1], lw[2], lw[3]);
}
static __device__ __forceinline__ unsigned pkbf_hi(float a, float b,
                                                   float& ra, float& rb) {
    __nv_bfloat16 h0 = __float2bfloat16(a);
    __nv_bfloat16 h1 = __float2bfloat16(b);
    ra = a - __bfloat162float(h0);
    rb = b - __bfloat162float(h1);
    return (unsigned)(*(unsigned short*)&h0) | ((unsigned)(*(unsigned short*)&h1) << 16);
}
static __device__ __forceinline__ unsigned pkbf(float a, float b) {
    __nv_bfloat16 h0 = __float2bfloat16(a);
    __nv_bfloat16 h1 = __float2bfloat16(b);
    return (unsigned)(*(unsigned short*)&h0) | ((unsigned)(*(unsigned short*)&h1) << 16);
}

// ---------------- weight split conversion (tiny) --------------------------------
__global__ void conv_w_k(const float* __restrict__ w) {
    int i = blockIdx.x * blockDim.x + threadIdx.x;
    if (i < 768 * 128) {
        float v = w[i];
        __nv_bfloat16 h = __float2bfloat16(v);
        g_wh[i] = h;
        g_wl[i] = __float2bfloat16(v - __bfloat162float(h));
    }
}

// ---------------- HMMA split-bf16 GEMM: C = A[M,128] @ W[N,128]^T + b -----------
__global__ __launch_bounds__(256, 1)
void gemm_mma(const float* __restrict__ x, const float* __restrict__ bih,
              const float* __restrict__ bhh, int which)
{
    const float* Asrc = which ? g_h1 : x;
    float*       C    = which ? g_g2 : g_g1;
    const int N    = which ? 256 : 512;
    const int NBLK = which ? 2 : 4;
    const int boff = which ? 512 : 0;
    const int brow = which ? 512 : 0;

    extern __shared__ __align__(1024) char smem[];
    char* sAh = smem;
    char* sAl = smem + 32768;
    char* sBh = smem + 65536;
    char* sBl = smem + 98304;
    const uint32_t aAh = smem_u32(sAh), aAl = smem_u32(sAl);
    const uint32_t aBh = smem_u32(sBh), aBl = smem_u32(sBl);

    const int tid  = threadIdx.x;
    const int lane = tid & 31;
    const int wid  = tid >> 5;
    const size_t mBase = (size_t)blockIdx.x * 128;

    {
        const int ck = tid & 15;
        const int r0 = (tid >> 4) * 8;
#pragma unroll
        for (int i = 0; i < 8; i++) {
            int r = r0 + i;
            float vbuf[8];
            const float4* src = (const float4*)(Asrc + (mBase + r) * 128 + ck * 8);
            float4 v0 = src[0], v1 = src[1];
            vbuf[0] = v0.x; vbuf[1] = v0.y; vbuf[2] = v0.z; vbuf[3] = v0.w;
            vbuf[4] = v1.x; vbuf[5] = v1.y; vbuf[6] = v1.z; vbuf[7] = v1.w;
            uint4 hi, lo;
            split8(vbuf, hi, lo);
            int off = r * 256 + ((ck ^ (r & 7)) << 4);
            *(uint4*)(sAh + off) = hi;
            *(uint4*)(sAl + off) = lo;
        }
    }

    const int mW = (wid & 3) * 32;
    const int nW = (wid >> 2) * 64;

    for (int nb = 0; nb < NBLK; nb++) {
        __syncthreads();
        {
            const int ck = tid & 15;
            const int r0 = (tid >> 4) * 8;
#pragma unroll
            for (int i = 0; i < 8; i++) {
                int r = r0 + i;
                size_t srow = (size_t)(brow + nb * 128 + r) * 128 + ck * 8;
                uint4 bh = *(const uint4*)(g_wh + srow);
                uint4 bl = *(const uint4*)(g_wl + srow);
                int off = r * 256 + ((ck ^ (r & 7)) << 4);
                *(uint4*)(sBh + off) = bh;
                *(uint4*)(sBl + off) = bl;
            }
        }
        __syncthreads();

        float acc[2][8][4];
#pragma unroll
        for (int mt = 0; mt < 2; mt++)
#pragma unroll
            for (int nt = 0; nt < 8; nt++)
#pragma unroll
                for (int q = 0; q < 4; q++) acc[mt][nt][q] = 0.f;

#pragma unroll
        for (int kk = 0; kk < 8; kk++) {
            const int kc = kk * 2;

            uint32_t af[2][2][4];
#pragma unroll
            for (int mt = 0; mt < 2; mt++) {
                int row = mW + mt * 16 + (lane & 15);
                int ch  = kc + (lane >> 4);
                uint32_t off = row * 256 + (((unsigned)(ch ^ (row & 7))) << 4);
                LDSM4(af[0][mt][0], af[0][mt][1], af[0][mt][2], af[0][mt][3], aAh + off);
                LDSM4(af[1][mt][0], af[1][mt][1], af[1][mt][2], af[1][mt][3], aAl + off);
            }

            uint32_t bf[2][8][2];
#pragma unroll
            for (int bt = 0; bt < 4; bt++) {
                int row = nW + bt * 16 + (lane & 7) + ((lane >> 4) << 3);
                int ch  = kc + ((lane >> 3) & 1);
                uint32_t off = row * 256 + (((unsigned)(ch ^ (row & 7))) << 4);
                uint32_t r0, r1, r2, r3;
                LDSM4(r0, r1, r2, r3, aBh + off);
                bf[0][2 * bt][0] = r0; bf[0][2 * bt][1] = r1;
                bf[0][2 * bt + 1][0] = r2; bf[0][2 * bt + 1][1] = r3;
                LDSM4(r0, r1, r2, r3, aBl + off);
                bf[1][2 * bt][0] = r0; bf[1][2 * bt][1] = r1;
                bf[1][2 * bt + 1][0] = r2; bf[1][2 * bt + 1][1] = r3;
            }

#pragma unroll
            for (int mt = 0; mt < 2; mt++)
#pragma unroll
                for (int nt = 0; nt < 8; nt++) {
                    mma16816(acc[mt][nt], af[0][mt], bf[0][nt]);
                    mma16816(acc[mt][nt], af[0][mt], bf[1][nt]);
                    mma16816(acc[mt][nt], af[1][mt], bf[0][nt]);
                }
        }

#pragma unroll
        for (int nt = 0; nt < 8; nt++) {
            int col = nb * 128 + nW + nt * 8 + (lane & 3) * 2;
            float b0 = bih[boff + col]     + bhh[boff + col];
            float b1 = bih[boff + col + 1] + bhh[boff + col + 1];
#pragma unroll
            for (int mt = 0; mt < 2; mt++) {
                size_t row = mBase + mW + mt * 16 + (lane >> 2);
                float2 v01 = make_float2(acc[mt][nt][0] + b0, acc[mt][nt][1] + b1);
                float2 v23 = make_float2(acc[mt][nt][2] + b0, acc[mt][nt][3] + b1);
                *(float2*)&C[row * N + col]       = v01;
                *(float2*)&C[(row + 8) * N + col] = v23;
            }
        }
    }
}

// ---------------- HMMA recurrence: TB=16 rows/CTA, h in smem split-bf16 ----------
// which=0: layer1 (dir = blockIdx.y), gx=g_g1, writes g_h1 each step
// which=1: layer2-fwd, gx=g_g2, writes g_h2 at t=T-1
// smem: Wh/Wl [256][64] bf16 swizzled (64KB) + hA double-buffered hi/lo (8KB)
//       + dump [16][260] fp32 (16640B)   => 90368B dynamic
#define REC_SMEM (65536 + 8192 + 16 * 260 * 4)
__global__ __launch_bounds__(256, 1)
void rec_mma_k(const float* __restrict__ whh, int which)
{
    extern __shared__ __align__(1024) char rsm[];
    char*  sWh = rsm;                         // 32KB
    char*  sWl = rsm + 32768;                 // 32KB
    char*  sHa = rsm + 65536;                 // 4 buffers x 2KB: [buf][hi|lo]
    float* sD  = (float*)(rsm + 65536 + 8192);  // [16][260]

    const int dir = blockIdx.y;
    const int b0  = blockIdx.x * RTB;
    const int tid = threadIdx.x;
    const int lane = tid & 31;
    const int wid  = tid >> 5;
    const int nW   = wid * 32;

    // ---- stage w_hh (this layer/dir) as split-bf16, swizzled 128B rows ----------
    {
        const int wrow = (which ? 512 : dir * 256) + tid;   // one gate row per thread
        const float* wr = whh + (size_t)wrow * 64;
#pragma unroll
        for (int ck = 0; ck < 8; ck++) {
            float vbuf[8];
            float4 v0 = *(const float4*)(wr + ck * 8);
            float4 v1 = *(const float4*)(wr + ck * 8 + 4);
            vbuf[0] = v0.x; vbuf[1] = v0.y; vbuf[2] = v0.z; vbuf[3] = v0.w;
            vbuf[4] = v1.x; vbuf[5] = v1.y; vbuf[6] = v1.z; vbuf[7] = v1.w;
            uint4 hi, lo;
            split8(vbuf, hi, lo);
            int off = tid * 128 + ((ck ^ (tid & 7)) << 4);
            *(uint4*)(sWh + off) = hi;
            *(uint4*)(sWl + off) = lo;
        }
    }
    // zero h staging (both buffers, both splits)
    for (int i = tid; i < 8192 / 4; i += 256) ((uint32_t*)sHa)[i] = 0;

    // ---- epilogue identity: 4 cells (er, j0..j0+3) ------------------------------
    const int er = tid >> 4;
    const int j0 = (tid & 15) * 4;
    const int gw = which ? 256 : 512;
    const float* gbe = which
        ? (g_g2 + (size_t)(b0 + er) * SEQT * 256 + j0)
        : (g_g1 + (size_t)(b0 + er) * SEQT * 512 + (size_t)dir * 256 + j0);

    float gxe[16];
    {
        const int t0 = (!which && dir) ? (SEQT - 1) : 0;
#pragma unroll
        for (int i = 0; i < 4; i++)
            *(float4*)(gxe + 4 * i) = *(const float4*)(gbe + (size_t)t0 * gw + i * 64);
    }
    __syncthreads();

    const uint32_t aWh = smem_u32(sWh), aWl = smem_u32(sWl);
    float cst[4] = {0.f, 0.f, 0.f, 0.f};
    int buf = 0;

    for (int tt = 0; tt < SEQT; tt++) {
        const int t   = (!which && dir) ? (SEQT - 1 - tt) : tt;
        const int ttn = (tt < SEQT - 1) ? (tt + 1) : tt;
        const int tn  = (!which && dir) ? (SEQT - 1 - ttn) : ttn;

        // prefetch next gx (4 x LDG.128)
        float gxf[16];
#pragma unroll
        for (int i = 0; i < 4; i++)
            *(float4*)(gxf + 4 * i) = *(const float4*)(gbe + (size_t)tn * gw + i * 64);

        // ---- matvec: h[16x64] @ W[256x64]^T via HMMA, 3 split products ----------
        const uint32_t aHi = smem_u32(sHa + buf * 4096);
        const uint32_t aLo = aHi + 2048;

        float acc[4][4];
#pragma unroll
        for (int nt = 0; nt < 4; nt++)
#pragma unroll
            for (int q = 0; q < 4; q++) acc[nt][q] = 0.f;

#pragma unroll
        for (int ks = 0; ks < 4; ks++) {
            const int kc = ks * 2;
            uint32_t ah[4], al[4];
            {
                int row = lane & 15;
                int ch  = kc + (lane >> 4);
                uint32_t off = row * 128 + (((unsigned)(ch ^ (row & 7))) << 4);
                LDSM4(ah[0], ah[1], ah[2], ah[3], aHi + off);
                LDSM4(al[0], al[1], al[2], al[3], aLo + off);
            }
            uint32_t bh[4][2], bl[4][2];
#pragma unroll
            for (int bt = 0; bt < 2; bt++) {
                int row = nW + bt * 16 + (lane & 7) + ((lane >> 4) << 3);
                int ch  = kc + ((lane >> 3) & 1);
                uint32_t off = row * 128 + (((unsigned)(ch ^ (row & 7))) << 4);
                uint32_t r0, r1, r2, r3;
                LDSM4(r0, r1, r2, r3, aWh + off);
                bh[2 * bt][0] = r0; bh[2 * bt][1] = r1;
                bh[2 * bt + 1][0] = r2; bh[2 * bt + 1][1] = r3;
                LDSM4(r0, r1, r2, r3, aWl + off);
                bl[2 * bt][0] = r0; bl[2 * bt][1] = r1;
                bl[2 * bt + 1][0] = r2; bl[2 * bt + 1][1] = r3;
            }
#pragma unroll
            for (int nt = 0; nt < 4; nt++) {
                mma16816(acc[nt], ah, bh[nt]);   // hh
                mma16816(acc[nt], ah, bl[nt]);   // hl
                mma16816(acc[nt], al, bh[nt]);   // lh
            }
        }

        // dump acc to smem [row][gate]
#pragma unroll
        for (int nt = 0; nt < 4; nt++) {
            int col = nW + nt * 8 + (lane & 3) * 2;
            int row = lane >> 2;
            *(float2*)&sD[row * 260 + col]       = make_float2(acc[nt][0], acc[nt][1]);
            *(float2*)&sD[(row + 8) * 260 + col] = make_float2(acc[nt][2], acc[nt][3]);
        }
        __syncthreads();

        // ---- epilogue: 4 cells (er, j0..j0+3) -----------------------------------
        {
            float xi4[4], xf4[4], xg4[4], xo4[4];
            *(float4*)xi4 = *(const float4*)&sD[er * 260 + j0];
            *(float4*)xf4 = *(const float4*)&sD[er * 260 + 64 + j0];
            *(float4*)xg4 = *(const float4*)&sD[er * 260 + 128 + j0];
            *(float4*)xo4 = *(const float4*)&sD[er * 260 + 192 + j0];
            float hv[4];
#pragma unroll
            for (int c = 0; c < 4; c++) {
                float iv = sigf(xi4[c] + gxe[c]);
                float fv = sigf(xf4[c] + gxe[4 + c]);
                float gv = tnhf(xg4[c] + gxe[8 + c]);
                float ov = sigf(xo4[c] + gxe[12 + c]);
                cst[c] = fv * cst[c] + iv * gv;
                hv[c] = ov * tnhf(cst[c]);
            }
            // write h split-bf16 into next buffer (swizzled), 4 bf16 = 8B per split
            float r0, r1, r2, r3;
            unsigned h01 = pkbf_hi(hv[0], hv[1], r0, r1);
            unsigned h23 = pkbf_hi(hv[2], hv[3], r2, r3);
            unsigned l01 = pkbf(r0, r1);
            unsigned l23 = pkbf(r2, r3);
            int ck  = j0 >> 3;
            int sub = (j0 * 2) & 8;
            uint32_t off = er * 128 + (((unsigned)(ck ^ (er & 7))) << 4) + sub;
            char* dst = sHa + (buf ^ 1) * 4096;
            *(uint2*)(dst + off)        = make_uint2(h01, h23);
            *(uint2*)(dst + 2048 + off) = make_uint2(l01, l23);

            if (!which) {
                *(float4*)&g_h1[((size_t)(b0 + er) * SEQT + t) * 128 + dir * 64 + j0] =
                    make_float4(hv[0], hv[1], hv[2], hv[3]);
            } else if (tt == SEQT - 1) {
                *(float4*)&g_h2[(b0 + er) * 64 + j0] =
                    make_float4(hv[0], hv[1], hv[2], hv[3]);
            }
        }
#pragma unroll
        for (int i = 0; i < 16; i++) gxe[i] = gxf[i];
        buf ^= 1;
        __syncthreads();
    }
}

// ---------------- final: 1-step layer2-bwd at t=T-1 + FC head -------------------
__global__ void final_k(const float* __restrict__ wih, const float* __restrict__ bih,
                        const float* __restrict__ bhh, const float* __restrict__ fcw,
                        const float* __restrict__ fcb, float* __restrict__ out)
{
    const int b = blockIdx.x;
    const int j = threadIdx.x;   // 64 threads

    __shared__ alignas(16) float xr[128];
    __shared__ float red[64];

    xr[j]      = g_h1[((size_t)b * SEQT + (SEQT - 1)) * 128 + j];
    xr[j + 64] = g_h1[((size_t)b * SEQT + (SEQT - 1)) * 128 + 64 + j];
    __syncthreads();

    const float* wi = wih + 98304 + (size_t)j * 128;
    const float* wg = wih + 98304 + (size_t)(128 + j) * 128;
    const float* wo = wih + 98304 + (size_t)(192 + j) * 128;
    float ai = bih[768 + j]       + bhh[768 + j];
    float ag = bih[768 + 128 + j] + bhh[768 + 128 + j];
    float ao = bih[768 + 192 + j] + bhh[768 + 192 + j];
#pragma unroll 8
    for (int k = 0; k < 128; k += 4) {
        float4 xv = *(const float4*)&xr[k];
        float4 a  = *(const float4*)&wi[k];
        float4 gq = *(const float4*)&wg[k];
        float4 oq = *(const float4*)&wo[k];
        ai += xv.x * a.x  + xv.y * a.y  + xv.z * a.z  + xv.w * a.w;
        ag += xv.x * gq.x + xv.y * gq.y + xv.z * gq.z + xv.w * gq.w;
        ao += xv.x * oq.x + xv.y * oq.y + xv.z * oq.z + xv.w * oq.w;
    }
    float c  = sigf(ai) * tnhf(ag);
    float hb = sigf(ao) * tnhf(c);

    red[j] = fcw[j] * g_h2[b * 64 + j] + fcw[64 + j] * hb;
    __syncthreads();
    if (j < 32) {
        float v = red[j] + red[j + 32];
#pragma unroll
        for (int o = 16; o; o >>= 1) v += __shfl_down_sync(0xffffffffu, v, o);
        if (j == 0) out[b] = v + fcb[0];
    }
}

// ---------------- launch --------------------------------------------------------
extern "C" void kernel_launch(void* const* d_in, const int* in_sizes, int n_in,
                              void* d_out, int out_size)
{
    (void)in_sizes; (void)n_in; (void)out_size;
    const float* x    = (const float*)d_in[0];
    const float* w_ih = (const float*)d_in[1];
    const float* w_hh = (const float*)d_in[2];
    const float* b_ih = (const float*)d_in[3];
    const float* b_hh = (const float*)d_in[4];
    const float* fc_w = (const float*)d_in[5];
    const float* fc_b = (const float*)d_in[6];
    float* out = (float*)d_out;

    const int gemm_smem = 131072;
    cudaFuncSetAttribute(gemm_mma, cudaFuncAttributeMaxDynamicSharedMemorySize, gemm_smem);
    cudaFuncSetAttribute(rec_mma_k, cudaFuncAttributeMaxDynamicSharedMemorySize, REC_SMEM);

    // 0) split-bf16 weight conversion (tiny)
    conv_w_k<<<384, 256>>>(w_ih);
    // 1) layer1 input projection, both dirs (N=512), HMMA split-bf16
    gemm_mma<<<4096, 256, gemm_smem>>>(x, b_ih, b_hh, 0);
    // 2) layer1 recurrence (fwd + bwd), HMMA, TB=16
    rec_mma_k<<<dim3(32, 2), 256, REC_SMEM>>>(w_hh, 0);
    // 3) layer2-fwd input projection (N=256), HMMA split-bf16
    gemm_mma<<<4096, 256, gemm_smem>>>(x, b_ih, b_hh, 1);
    // 4) layer2-fwd recurrence, HMMA, TB=16
    rec_mma_k<<<dim3(32, 1), 256, REC_SMEM>>>(w_hh, 1);
    // 5) layer2-bwd single step at t=T-1 + FC head
    final_k<<<dim3(512, 1), 64>>>(w_ih, b_ih, b_hh, fc_w, fc_b, out);
}